// round 4
// baseline (speedup 1.0000x reference)
#include <cuda_runtime.h>

#define N_COLS  65536
#define C_DIM   256
#define N_BATCH 2
#define SCALE   0.17677669529663687f   // 32^-0.5

// ---------------- scratch (static device arrays; no allocation) ----------------
__device__ float g_numer[N_BATCH][4][32][32];      // sum_n exp(k[d,n]) * v[e,n]
__device__ float g_sumexp[N_BATCH][128];           // sum_n exp(k[d,n])
__device__ float g_t1[N_BATCH][128][C_DIM];        // BlockDiag(ctx^T) @ Wq
__device__ float g_weff[N_BATCH][C_DIM][C_DIM];    // scale * Wout @ T1

// ---------------- zero the accumulators ----------------
__global__ void zero_accum_kernel() {
    int t = blockIdx.x * blockDim.x + threadIdx.x;
    float* numer = &g_numer[0][0][0][0];
    if (t < N_BATCH * 4 * 32 * 32) numer[t] = 0.0f;
    float* se = &g_sumexp[0][0];
    if (t < N_BATCH * 128) se[t] = 0.0f;
}

// =====================================================================
// Fused: kv-tile GEMM (Wkv[256x256] @ x[:,n0:n0+64]) -> exp/outer-product
// reduction into g_numer / g_sumexp. No global kv scratch.
// grid: (N_COLS/64, N_BATCH), 256 threads.
// =====================================================================
__global__ __launch_bounds__(256, 2)
void kv_reduce_kernel(const float* __restrict__ Wqkv, const float* __restrict__ x)
{
    const int b  = blockIdx.y;
    const int n0 = blockIdx.x * 64;
    const float* A = Wqkv + 128 * C_DIM;                     // Wkv rows 128..383
    const float* B = x + (size_t)b * C_DIM * N_COLS;

    // one raw buffer, two phases:
    //   GEMM : As[2][16][256] (8192 f) + Bs[2][16][64] (2048 f)
    //   STAGE: tile[256][36]  (9216 f)
    __shared__ __align__(16) float smem[10240];
    float* As = smem;            // [buf*4096 + k*256 + m]
    float* Bs = smem + 8192;     // [buf*1024 + k*64  + n]

    const int t  = threadIdx.x;
    const int ty = t >> 3;       // 0..31  -> rows ty*8..ty*8+7  (m: 0..255)
    const int tx = t & 7;        // 0..7   -> cols tx*8..tx*8+7  (n: 0..63)

    float4 aReg[4];
    float4 bReg;

    // ---- prologue: k-tile 0 ----
    {
        #pragma unroll
        for (int i = 0; i < 4; i++) {
            int idx = t + i * 256;
            int row = idx >> 2, q4 = idx & 3;
            aReg[i] = *reinterpret_cast<const float4*>(&A[row * C_DIM + q4 * 4]);
        }
        int brow = t >> 4, bcv = t & 15;
        bReg = *reinterpret_cast<const float4*>(&B[brow * N_COLS + n0 + bcv * 4]);

        #pragma unroll
        for (int i = 0; i < 4; i++) {
            int idx = t + i * 256;
            int row = idx >> 2, q4 = idx & 3;
            As[(q4 * 4 + 0) * 256 + row] = aReg[i].x;
            As[(q4 * 4 + 1) * 256 + row] = aReg[i].y;
            As[(q4 * 4 + 2) * 256 + row] = aReg[i].z;
            As[(q4 * 4 + 3) * 256 + row] = aReg[i].w;
        }
        *reinterpret_cast<float4*>(&Bs[brow * 64 + bcv * 4]) = bReg;
    }
    __syncthreads();

    float acc[8][8];
    #pragma unroll
    for (int i = 0; i < 8; i++)
        #pragma unroll
        for (int j = 0; j < 8; j++) acc[i][j] = 0.0f;

    #pragma unroll 1
    for (int kt = 0; kt < 16; kt++) {
        const int cur = kt & 1;
        if (kt < 15) {
            const int koff = (kt + 1) * 16;
            #pragma unroll
            for (int i = 0; i < 4; i++) {
                int idx = t + i * 256;
                int row = idx >> 2, q4 = idx & 3;
                aReg[i] = *reinterpret_cast<const float4*>(&A[row * C_DIM + koff + q4 * 4]);
            }
            int brow = t >> 4, bcv = t & 15;
            bReg = *reinterpret_cast<const float4*>(&B[(koff + brow) * N_COLS + n0 + bcv * 4]);
        }
        #pragma unroll
        for (int k = 0; k < 16; k++) {
            __align__(16) float af[8], bf[8];
            *reinterpret_cast<float4*>(&af[0]) = *reinterpret_cast<const float4*>(&As[cur * 4096 + k * 256 + ty * 8]);
            *reinterpret_cast<float4*>(&af[4]) = *reinterpret_cast<const float4*>(&As[cur * 4096 + k * 256 + ty * 8 + 4]);
            *reinterpret_cast<float4*>(&bf[0]) = *reinterpret_cast<const float4*>(&Bs[cur * 1024 + k * 64 + tx * 8]);
            *reinterpret_cast<float4*>(&bf[4]) = *reinterpret_cast<const float4*>(&Bs[cur * 1024 + k * 64 + tx * 8 + 4]);
            #pragma unroll
            for (int i = 0; i < 8; i++)
                #pragma unroll
                for (int j = 0; j < 8; j++)
                    acc[i][j] += af[i] * bf[j];
        }
        if (kt < 15) {
            const int nxt = cur ^ 1;
            #pragma unroll
            for (int i = 0; i < 4; i++) {
                int idx = t + i * 256;
                int row = idx >> 2, q4 = idx & 3;
                As[nxt * 4096 + (q4 * 4 + 0) * 256 + row] = aReg[i].x;
                As[nxt * 4096 + (q4 * 4 + 1) * 256 + row] = aReg[i].y;
                As[nxt * 4096 + (q4 * 4 + 2) * 256 + row] = aReg[i].z;
                As[nxt * 4096 + (q4 * 4 + 3) * 256 + row] = aReg[i].w;
            }
            int brow = t >> 4, bcv = t & 15;
            *reinterpret_cast<float4*>(&Bs[nxt * 1024 + brow * 64 + bcv * 4]) = bReg;
        }
        __syncthreads();
    }

    // ---- phase 2: stage tile (32 cols at a time) + outer-product reduce ----
    // rows 0..127 = k (store exp), rows 128..255 = v
    const int h  = t >> 6;          // head 0..3
    const int d  = (t & 63) >> 1;   // 0..31
    const int ep = t & 1;           // e half

    float racc[16];
    #pragma unroll
    for (int j = 0; j < 16; j++) racc[j] = 0.0f;
    float sume = 0.0f;

    #pragma unroll 1
    for (int ch = 0; ch < 2; ch++) {
        __syncthreads();            // previous phase/iteration done with smem
        if ((tx >> 2) == ch) {
            const int cc = (tx & 3) * 8;           // col within chunk
            #pragma unroll
            for (int i = 0; i < 8; i++) {
                const int m = ty * 8 + i;
                float v0 = acc[i][0], v1 = acc[i][1], v2 = acc[i][2], v3 = acc[i][3];
                float v4 = acc[i][4], v5 = acc[i][5], v6 = acc[i][6], v7 = acc[i][7];
                if (m < 128) {
                    v0 = __expf(v0); v1 = __expf(v1); v2 = __expf(v2); v3 = __expf(v3);
                    v4 = __expf(v4); v5 = __expf(v5); v6 = __expf(v6); v7 = __expf(v7);
                }
                *reinterpret_cast<float4*>(&smem[m * 36 + cc])     = make_float4(v0, v1, v2, v3);
                *reinterpret_cast<float4*>(&smem[m * 36 + cc + 4]) = make_float4(v4, v5, v6, v7);
            }
        }
        __syncthreads();
        #pragma unroll
        for (int n4 = 0; n4 < 8; n4++) {
            float4 ek = *reinterpret_cast<const float4*>(&smem[(h * 32 + d) * 36 + n4 * 4]);
            if (ep == 0) sume += (ek.x + ek.y) + (ek.z + ek.w);
            #pragma unroll
            for (int j = 0; j < 16; j++) {
                float4 vv = *reinterpret_cast<const float4*>(&smem[(128 + h * 32 + ep * 16 + j) * 36 + n4 * 4]);
                racc[j] += ek.x * vv.x + ek.y * vv.y + ek.z * vv.z + ek.w * vv.w;
            }
        }
    }

    #pragma unroll
    for (int j = 0; j < 16; j++)
        atomicAdd(&g_numer[b][h][d][ep * 16 + j], racc[j]);
    if (ep == 0)
        atomicAdd(&g_sumexp[b][h * 32 + d], sume);
}

// ---------------- T1[h*32+e][c] = sum_d (numer[h][d][e]/sumexp[h*32+d]) * Wq[h*32+d][c]
__global__ __launch_bounds__(256)
void t1_kernel(const float* __restrict__ Wqkv)
{
    const int r = blockIdx.x;   // 0..127 (= h*32 + e)
    const int b = blockIdx.y;
    const int h = r >> 5, e = r & 31;
    __shared__ float ctx[32];
    const int t = threadIdx.x;
    if (t < 32) ctx[t] = g_numer[b][h][t][e] / g_sumexp[b][h * 32 + t];
    __syncthreads();
    float s = 0.0f;
    #pragma unroll
    for (int d = 0; d < 32; d++)
        s += ctx[d] * __ldg(&Wqkv[(h * 32 + d) * C_DIM + t]);   // q rows = Wqkv rows 0..127
    g_t1[b][r][t] = s;
}

// ---------------- W_eff[o][c] = scale * sum_e Wout[o][e] * T1[e][c]
__global__ __launch_bounds__(256)
void weff_kernel(const float* __restrict__ Wout)
{
    const int o = blockIdx.x;   // 0..255
    const int b = blockIdx.y;
    __shared__ float wo[128];
    const int t = threadIdx.x;
    if (t < 128) wo[t] = __ldg(&Wout[o * 128 + t]);
    __syncthreads();
    float s = 0.0f;
    #pragma unroll 16
    for (int e = 0; e < 128; e++)
        s += wo[e] * g_t1[b][e][t];
    g_weff[b][o][t] = s * SCALE;
}

// =====================================================================
// Final SGEMM: y[b] = W_eff[b](256x256) @ x[b](256x65536) + b_out
// 128x128 tiles, double-buffered, 8x8 microtile.
// =====================================================================
__global__ __launch_bounds__(256, 2)
void out_gemm_kernel(const float* __restrict__ x,
                     float* __restrict__ y,
                     const float* __restrict__ bias)
{
    const int n0 = blockIdx.x * 128;
    const int m0 = blockIdx.y * 128;
    const int b  = blockIdx.z;

    const float* A = &g_weff[b][0][0];
    const float* B = x + (size_t)b * C_DIM * N_COLS;
    float* C = y + (size_t)b * C_DIM * N_COLS;

    __shared__ __align__(16) float As[2][16][128];   // [k][m]
    __shared__ __align__(16) float Bs[2][16][128];   // [k][n]

    const int t  = threadIdx.x;
    const int ty = t >> 4, tx = t & 15;

    float4 aReg[2], bReg[2];

    #pragma unroll
    for (int i = 0; i < 2; i++) {
        int idx = t + i * 256;
        int row = idx >> 2, cv = idx & 3;
        aReg[i] = *reinterpret_cast<const float4*>(&A[(m0 + row) * C_DIM + cv * 4]);
        int brow = idx >> 5, bcv = idx & 31;
        bReg[i] = *reinterpret_cast<const float4*>(&B[brow * N_COLS + n0 + bcv * 4]);
    }
    #pragma unroll
    for (int i = 0; i < 2; i++) {
        int idx = t + i * 256;
        int row = idx >> 2, cv = idx & 3;
        As[0][cv * 4 + 0][row] = aReg[i].x;
        As[0][cv * 4 + 1][row] = aReg[i].y;
        As[0][cv * 4 + 2][row] = aReg[i].z;
        As[0][cv * 4 + 3][row] = aReg[i].w;
        int brow = idx >> 5, bcv = idx & 31;
        *reinterpret_cast<float4*>(&Bs[0][brow][bcv * 4]) = bReg[i];
    }
    __syncthreads();

    float acc[8][8];
    #pragma unroll
    for (int i = 0; i < 8; i++)
        #pragma unroll
        for (int j = 0; j < 8; j++) acc[i][j] = 0.0f;

    #pragma unroll 1
    for (int kt = 0; kt < 16; kt++) {
        const int cur = kt & 1;
        if (kt < 15) {
            const int koff = (kt + 1) * 16;
            #pragma unroll
            for (int i = 0; i < 2; i++) {
                int idx = t + i * 256;
                int row = idx >> 2, cv = idx & 3;
                aReg[i] = *reinterpret_cast<const float4*>(&A[(m0 + row) * C_DIM + koff + cv * 4]);
                int brow = idx >> 5, bcv = idx & 31;
                bReg[i] = *reinterpret_cast<const float4*>(&B[(koff + brow) * N_COLS + n0 + bcv * 4]);
            }
        }
        #pragma unroll
        for (int k = 0; k < 16; k++) {
            __align__(16) float af[8], bf[8];
            *reinterpret_cast<float4*>(&af[0]) = *reinterpret_cast<const float4*>(&As[cur][k][ty * 8]);
            *reinterpret_cast<float4*>(&af[4]) = *reinterpret_cast<const float4*>(&As[cur][k][ty * 8 + 4]);
            *reinterpret_cast<float4*>(&bf[0]) = *reinterpret_cast<const float4*>(&Bs[cur][k][tx * 8]);
            *reinterpret_cast<float4*>(&bf[4]) = *reinterpret_cast<const float4*>(&Bs[cur][k][tx * 8 + 4]);
            #pragma unroll
            for (int i = 0; i < 8; i++)
                #pragma unroll
                for (int j = 0; j < 8; j++)
                    acc[i][j] += af[i] * bf[j];
        }
        if (kt < 15) {
            const int nxt = cur ^ 1;
            #pragma unroll
            for (int i = 0; i < 2; i++) {
                int idx = t + i * 256;
                int row = idx >> 2, cv = idx & 3;
                As[nxt][cv * 4 + 0][row] = aReg[i].x;
                As[nxt][cv * 4 + 1][row] = aReg[i].y;
                As[nxt][cv * 4 + 2][row] = aReg[i].z;
                As[nxt][cv * 4 + 3][row] = aReg[i].w;
                int brow = idx >> 5, bcv = idx & 31;
                *reinterpret_cast<float4*>(&Bs[nxt][brow][bcv * 4]) = bReg[i];
            }
        }
        __syncthreads();
    }

    #pragma unroll
    for (int i = 0; i < 8; i++) {
        const int row = m0 + ty * 8 + i;
        const float bv = __ldg(&bias[row]);
        float4 o0 = make_float4(acc[i][0] + bv, acc[i][1] + bv, acc[i][2] + bv, acc[i][3] + bv);
        float4 o1 = make_float4(acc[i][4] + bv, acc[i][5] + bv, acc[i][6] + bv, acc[i][7] + bv);
        *reinterpret_cast<float4*>(&C[row * N_COLS + n0 + tx * 8])     = o0;
        *reinterpret_cast<float4*>(&C[row * N_COLS + n0 + tx * 8 + 4]) = o1;
    }
}

// ---------------- launch ----------------
extern "C" void kernel_launch(void* const* d_in, const int* in_sizes, int n_in,
                              void* d_out, int out_size)
{
    const float* x    = (const float*)d_in[0];   // (2, 256, 16, 64, 64)
    const float* Wqkv = (const float*)d_in[1];   // (384, 256)
    const float* Wout = (const float*)d_in[2];   // (256, 128)
    const float* bout = (const float*)d_in[3];   // (256,)
    float* y = (float*)d_out;                    // (2, 256, 16, 64, 64)

    zero_accum_kernel<<<32, 256>>>();

    kv_reduce_kernel<<<dim3(N_COLS / 64, N_BATCH), 256>>>(Wqkv, x);

    t1_kernel<<<dim3(128, N_BATCH), 256>>>(Wqkv);
    weff_kernel<<<dim3(C_DIM, N_BATCH), 256>>>(Wout);

    out_gemm_kernel<<<dim3(N_COLS / 128, 2, N_BATCH), 256>>>(x, y, bout);
}

// round 6
// speedup vs baseline: 1.0213x; 1.0213x over previous
#include <cuda_runtime.h>
#include <cuda_bf16.h>
#include <cstdint>

#define N_COLS  65536
#define C_DIM   256
#define N_BATCH 2
#define SCALE   0.17677669529663687f   // 32^-0.5

// ---------------- scratch (static device arrays; no allocation) ----------------
__device__ float g_numer[N_BATCH][4][32][32];      // sum_n exp(k[d,n]) * v[e,n]
__device__ float g_sumexp[N_BATCH][128];           // sum_n exp(k[d,n])
__device__ float g_t1[N_BATCH][128][C_DIM];        // BlockDiag(ctx^T) @ Wq
__device__ float g_weff[N_BATCH][C_DIM][C_DIM];    // scale * Wout @ T1

// A-operand fragment storage: [split(hi/lo)][k_atom(16)][m_atom(16)][lane(32)][reg(4)]
__device__ uint32_t g_WkvA[2][16][16][32][4];
__device__ uint32_t g_WeffA[N_BATCH][2][16][16][32][4];

// ---------------- helpers ----------------
__device__ __forceinline__ uint32_t pack_bf16(float a, float b) {
    __nv_bfloat162 t = __floats2bfloat162_rn(a, b);   // .x = a (low half)
    return *reinterpret_cast<uint32_t*>(&t);
}

__device__ __forceinline__ void split_bf16(float v, __nv_bfloat16& h, __nv_bfloat16& l) {
    h = __float2bfloat16(v);
    l = __float2bfloat16(v - __bfloat162float(h));
}

__device__ __forceinline__ void ldsm_x4_t(uint32_t r[4], uint32_t addr) {
    asm volatile("ldmatrix.sync.aligned.m8n8.x4.trans.shared.b16 {%0,%1,%2,%3}, [%4];"
        : "=r"(r[0]), "=r"(r[1]), "=r"(r[2]), "=r"(r[3]) : "r"(addr));
}

__device__ __forceinline__ void mma_bf16(float c[4], const uint32_t a[4], const uint32_t b[2]) {
    asm volatile("mma.sync.aligned.m16n8k16.row.col.f32.bf16.bf16.f32 "
        "{%0,%1,%2,%3}, {%4,%5,%6,%7}, {%8,%9}, {%0,%1,%2,%3};"
        : "+f"(c[0]), "+f"(c[1]), "+f"(c[2]), "+f"(c[3])
        : "r"(a[0]), "r"(a[1]), "r"(a[2]), "r"(a[3]), "r"(b[0]), "r"(b[1]));
}

// ---------------- zero the accumulators ----------------
__global__ void zero_accum_kernel() {
    int t = blockIdx.x * blockDim.x + threadIdx.x;
    float* numer = &g_numer[0][0][0][0];
    if (t < N_BATCH * 4 * 32 * 32) numer[t] = 0.0f;
    float* se = &g_sumexp[0][0];
    if (t < N_BATCH * 128) se[t] = 0.0f;
}

// ---------------- prep: Wkv -> hi/lo bf16 in A-fragment layout ----------------
// a0:(g, k0) a1:(g+8, k0) a2:(g, k0+8) a3:(g+8, k0+8); each reg packs (k, k+1)
__global__ void wkv_prep_kernel(const float* __restrict__ Wqkv) {
    int t = blockIdx.x * blockDim.x + threadIdx.x;
    if (t >= 16 * 16 * 32) return;
    int lane = t & 31, ma = (t >> 5) & 15, ka = t >> 9;
    int g = lane >> 2, tg = lane & 3;
    const float* W = Wqkv + 128 * C_DIM;    // Wkv rows
    #pragma unroll
    for (int r = 0; r < 4; r++) {
        int row = ma * 16 + g + (r & 1) * 8;
        int col = ka * 16 + tg * 2 + (r >> 1) * 8;
        float v0 = W[row * C_DIM + col], v1 = W[row * C_DIM + col + 1];
        __nv_bfloat16 h0, l0, h1, l1;
        split_bf16(v0, h0, l0); split_bf16(v1, h1, l1);
        g_WkvA[0][ka][ma][lane][r] = pack_bf16(__bfloat162float(h0), __bfloat162float(h1));
        g_WkvA[1][ka][ma][lane][r] = pack_bf16(__bfloat162float(l0), __bfloat162float(l1));
    }
}

// ---------------- prep: W_eff -> fragment layout (per batch) ----------------
__global__ void weff_prep_kernel() {
    int t = blockIdx.x * blockDim.x + threadIdx.x;
    int b = blockIdx.y;
    if (t >= 16 * 16 * 32) return;
    int lane = t & 31, ma = (t >> 5) & 15, ka = t >> 9;
    int g = lane >> 2, tg = lane & 3;
    const float* W = &g_weff[b][0][0];
    #pragma unroll
    for (int r = 0; r < 4; r++) {
        int row = ma * 16 + g + (r & 1) * 8;
        int col = ka * 16 + tg * 2 + (r >> 1) * 8;
        float v0 = W[row * C_DIM + col], v1 = W[row * C_DIM + col + 1];
        __nv_bfloat16 h0, l0, h1, l1;
        split_bf16(v0, h0, l0); split_bf16(v1, h1, l1);
        g_WeffA[b][0][ka][ma][lane][r] = pack_bf16(__bfloat162float(h0), __bfloat162float(h1));
        g_WeffA[b][1][ka][ma][lane][r] = pack_bf16(__bfloat162float(l0), __bfloat162float(l1));
    }
}

// =====================================================================
// Shared GEMM tile core: acc[2][8][4] += W(256x256) @ B[:, n0:n0+64]
// Split-bf16: Ah*Bh + Ah*Bl + Al*Bh, fp32 accum. 256 threads = 8 warps,
// warp w owns rows 32w..32w+31 (m-atoms 2w, 2w+1).
// smem usage: sxh[64][72] bf16 + sxl[64][72] bf16 (18432 B)
// =====================================================================
__device__ __forceinline__ void gemm_tile(
    const uint32_t* __restrict__ WAh, const uint32_t* __restrict__ WAl,
    const float* __restrict__ B, int n0,
    char* smem, float acc[2][8][4], int t)
{
    const int lane = t & 31, w = t >> 5;
    __nv_bfloat16* sxh = reinterpret_cast<__nv_bfloat16*>(smem);
    __nv_bfloat16* sxl = sxh + 64 * 72;

    const int krow_ld = (lane & 7) + ((lane >> 3) & 1) * 8;   // within k-atom pair
    const int ncol_ld = (lane >> 4) * 8;

    #pragma unroll 1
    for (int c = 0; c < 4; c++) {
        __syncthreads();
        // load 64k x 64n fp32 chunk, split hi/lo into smem [k][n]
        #pragma unroll
        for (int i = 0; i < 4; i++) {
            int linear = t + i * 256;
            int k = linear >> 4, n4 = linear & 15;
            float4 v = *reinterpret_cast<const float4*>(&B[(size_t)(c * 64 + k) * N_COLS + n0 + n4 * 4]);
            __nv_bfloat16 h0, l0, h1, l1, h2, l2, h3, l3;
            split_bf16(v.x, h0, l0); split_bf16(v.y, h1, l1);
            split_bf16(v.z, h2, l2); split_bf16(v.w, h3, l3);
            uint2 ph = make_uint2(pack_bf16(__bfloat162float(h0), __bfloat162float(h1)),
                                  pack_bf16(__bfloat162float(h2), __bfloat162float(h3)));
            uint2 pl = make_uint2(pack_bf16(__bfloat162float(l0), __bfloat162float(l1)),
                                  pack_bf16(__bfloat162float(l2), __bfloat162float(l3)));
            *reinterpret_cast<uint2*>(&sxh[k * 72 + n4 * 4]) = ph;
            *reinterpret_cast<uint2*>(&sxl[k * 72 + n4 * 4]) = pl;
        }
        __syncthreads();

        #pragma unroll
        for (int ka = 0; ka < 4; ka++) {
            const int kg = c * 4 + ka;
            const uint4* pah = reinterpret_cast<const uint4*>(WAh + ((size_t)(kg * 16 + 2 * w) * 32 + lane) * 4);
            const uint4* pal = reinterpret_cast<const uint4*>(WAl + ((size_t)(kg * 16 + 2 * w) * 32 + lane) * 4);
            uint4 ah0 = pah[0], ah1 = pah[32];
            uint4 al0 = pal[0], al1 = pal[32];

            const int kr = ka * 16 + krow_ld;
            #pragma unroll
            for (int p = 0; p < 4; p++) {
                uint32_t addr_h = (uint32_t)__cvta_generic_to_shared(&sxh[kr * 72 + p * 16 + ncol_ld]);
                uint32_t addr_l = (uint32_t)__cvta_generic_to_shared(&sxl[kr * 72 + p * 16 + ncol_ld]);
                uint32_t bh[4], bl[4];
                ldsm_x4_t(bh, addr_h);
                ldsm_x4_t(bl, addr_l);
                const uint32_t* a_h0 = reinterpret_cast<const uint32_t*>(&ah0);
                const uint32_t* a_h1 = reinterpret_cast<const uint32_t*>(&ah1);
                const uint32_t* a_l0 = reinterpret_cast<const uint32_t*>(&al0);
                const uint32_t* a_l1 = reinterpret_cast<const uint32_t*>(&al1);
                // n-atom 2p  (regs bh[0..1]/bl[0..1]), n-atom 2p+1 (regs [2..3])
                mma_bf16(acc[0][2 * p],     a_h0, bh + 0);
                mma_bf16(acc[1][2 * p],     a_h1, bh + 0);
                mma_bf16(acc[0][2 * p + 1], a_h0, bh + 2);
                mma_bf16(acc[1][2 * p + 1], a_h1, bh + 2);
                mma_bf16(acc[0][2 * p],     a_h0, bl + 0);
                mma_bf16(acc[1][2 * p],     a_h1, bl + 0);
                mma_bf16(acc[0][2 * p + 1], a_h0, bl + 2);
                mma_bf16(acc[1][2 * p + 1], a_h1, bl + 2);
                mma_bf16(acc[0][2 * p],     a_l0, bh + 0);
                mma_bf16(acc[1][2 * p],     a_l1, bh + 0);
                mma_bf16(acc[0][2 * p + 1], a_l0, bh + 2);
                mma_bf16(acc[1][2 * p + 1], a_l1, bh + 2);
            }
        }
    }
}

// =====================================================================
// Fused kv GEMM (tensor cores) + exp/outer-product reduction
// =====================================================================
__global__ __launch_bounds__(256)
void kv_mma_kernel(const float* __restrict__ x)
{
    const int b  = blockIdx.y;
    const int n0 = blockIdx.x * 64;
    const int t  = threadIdx.x;
    __shared__ __align__(16) char smem[36864];   // max(18432 gemm, 36864 stage)

    float acc[2][8][4];
    #pragma unroll
    for (int i = 0; i < 2; i++)
        #pragma unroll
        for (int j = 0; j < 8; j++)
            #pragma unroll
            for (int r = 0; r < 4; r++) acc[i][j][r] = 0.0f;

    gemm_tile(&g_WkvA[0][0][0][0][0], &g_WkvA[1][0][0][0][0],
              x + (size_t)b * C_DIM * N_COLS, n0, smem, acc, t);

    // phase 2: stage 32 cols at a time (rows<128 = k -> exp), reduce
    float* stage = reinterpret_cast<float*>(smem);
    const int lane = t & 31, w = t >> 5, g = lane >> 2, tg = lane & 3;
    const int h = t >> 6, d = (t & 63) >> 1, ep = t & 1;

    float racc[16];
    #pragma unroll
    for (int j = 0; j < 16; j++) racc[j] = 0.0f;
    float sume = 0.0f;

    #pragma unroll 1
    for (int ch = 0; ch < 2; ch++) {
        __syncthreads();
        #pragma unroll
        for (int i = 0; i < 2; i++) {
            const int mrow = w * 32 + i * 16 + g;
            #pragma unroll
            for (int q = 0; q < 4; q++) {
                const int na = ch * 4 + q;
                float c0 = acc[i][na][0], c1 = acc[i][na][1];
                float c2 = acc[i][na][2], c3 = acc[i][na][3];
                if (w < 4) {   // k rows -> exp
                    c0 = __expf(c0); c1 = __expf(c1);
                    c2 = __expf(c2); c3 = __expf(c3);
                }
                const int col = q * 8 + tg * 2;
                *reinterpret_cast<float2*>(&stage[mrow * 36 + col])       = make_float2(c0, c1);
                *reinterpret_cast<float2*>(&stage[(mrow + 8) * 36 + col]) = make_float2(c2, c3);
            }
        }
        __syncthreads();
        #pragma unroll
        for (int n4 = 0; n4 < 8; n4++) {
            float4 ek = *reinterpret_cast<const float4*>(&stage[(h * 32 + d) * 36 + n4 * 4]);
            if (ep == 0) sume += (ek.x + ek.y) + (ek.z + ek.w);
            #pragma unroll
            for (int j = 0; j < 16; j++) {
                float4 vv = *reinterpret_cast<const float4*>(&stage[(128 + h * 32 + ep * 16 + j) * 36 + n4 * 4]);
                racc[j] += ek.x * vv.x + ek.y * vv.y + ek.z * vv.z + ek.w * vv.w;
            }
        }
    }

    #pragma unroll
    for (int j = 0; j < 16; j++)
        atomicAdd(&g_numer[b][h][d][ep * 16 + j], racc[j]);
    if (ep == 0)
        atomicAdd(&g_sumexp[b][h * 32 + d], sume);
}

// ---------------- T1[h*32+e][c] = sum_d (numer[h][d][e]/sumexp[h*32+d]) * Wq[h*32+d][c]
__global__ __launch_bounds__(256)
void t1_kernel(const float* __restrict__ Wqkv)
{
    const int r = blockIdx.x;
    const int b = blockIdx.y;
    const int h = r >> 5, e = r & 31;
    __shared__ float ctx[32];
    const int t = threadIdx.x;
    if (t < 32) ctx[t] = g_numer[b][h][t][e] / g_sumexp[b][h * 32 + t];
    __syncthreads();
    float s = 0.0f;
    #pragma unroll
    for (int d = 0; d < 32; d++)
        s += ctx[d] * __ldg(&Wqkv[(h * 32 + d) * C_DIM + t]);
    g_t1[b][r][t] = s;
}

// ---------------- W_eff[o][c] = scale * sum_e Wout[o][e] * T1[e][c]
__global__ __launch_bounds__(256)
void weff_kernel(const float* __restrict__ Wout)
{
    const int o = blockIdx.x;
    const int b = blockIdx.y;
    __shared__ float wo[128];
    const int t = threadIdx.x;
    if (t < 128) wo[t] = __ldg(&Wout[o * 128 + t]);
    __syncthreads();
    float s = 0.0f;
    #pragma unroll 16
    for (int e = 0; e < 128; e++)
        s += wo[e] * g_t1[b][e][t];
    g_weff[b][o][t] = s * SCALE;
}

// =====================================================================
// Final GEMM (tensor cores): y[b] = W_eff[b] @ x[b] + b_out
// =====================================================================
__global__ __launch_bounds__(256)
void out_mma_kernel(const float* __restrict__ x,
                    float* __restrict__ y,
                    const float* __restrict__ bias)
{
    const int b  = blockIdx.y;
    const int n0 = blockIdx.x * 64;
    const int t  = threadIdx.x;
    __shared__ __align__(16) char smem[36864];

    float acc[2][8][4];
    #pragma unroll
    for (int i = 0; i < 2; i++)
        #pragma unroll
        for (int j = 0; j < 8; j++)
            #pragma unroll
            for (int r = 0; r < 4; r++) acc[i][j][r] = 0.0f;

    gemm_tile(&g_WeffA[b][0][0][0][0][0], &g_WeffA[b][1][0][0][0][0],
              x + (size_t)b * C_DIM * N_COLS, n0, smem, acc, t);

    float* stage = reinterpret_cast<float*>(smem);
    float* C = y + (size_t)b * C_DIM * N_COLS;
    const int lane = t & 31, w = t >> 5, g = lane >> 2, tg = lane & 3;

    #pragma unroll 1
    for (int ch = 0; ch < 2; ch++) {
        __syncthreads();
        #pragma unroll
        for (int i = 0; i < 2; i++) {
            const int mrow = w * 32 + i * 16 + g;
            #pragma unroll
            for (int q = 0; q < 4; q++) {
                const int na = ch * 4 + q;
                const int col = q * 8 + tg * 2;
                *reinterpret_cast<float2*>(&stage[mrow * 36 + col])       = make_float2(acc[i][na][0], acc[i][na][1]);
                *reinterpret_cast<float2*>(&stage[(mrow + 8) * 36 + col]) = make_float2(acc[i][na][2], acc[i][na][3]);
            }
        }
        __syncthreads();
        #pragma unroll
        for (int it = 0; it < 8; it++) {
            const int r = (t >> 3) + it * 32;
            float4 v = *reinterpret_cast<const float4*>(&stage[r * 36 + (t & 7) * 4]);
            const float bv = __ldg(&bias[r]);
            v.x += bv; v.y += bv; v.z += bv; v.w += bv;
            *reinterpret_cast<float4*>(&C[(size_t)r * N_COLS + n0 + ch * 32 + (t & 7) * 4]) = v;
        }
    }
}

// ---------------- launch ----------------
extern "C" void kernel_launch(void* const* d_in, const int* in_sizes, int n_in,
                              void* d_out, int out_size)
{
    const float* x    = (const float*)d_in[0];   // (2, 256, 16, 64, 64)
    const float* Wqkv = (const float*)d_in[1];   // (384, 256)
    const float* Wout = (const float*)d_in[2];   // (256, 128)
    const float* bout = (const float*)d_in[3];   // (256,)
    float* y = (float*)d_out;                    // (2, 256, 16, 64, 64)

    zero_accum_kernel<<<32, 256>>>();
    wkv_prep_kernel<<<32, 256>>>(Wqkv);

    kv_mma_kernel<<<dim3(N_COLS / 64, N_BATCH), 256>>>(x);

    t1_kernel<<<dim3(128, N_BATCH), 256>>>(Wqkv);
    weff_kernel<<<dim3(C_DIM, N_BATCH), 256>>>(Wout);
    weff_prep_kernel<<<dim3(32, N_BATCH), 256>>>();

    out_mma_kernel<<<dim3(N_COLS / 64, N_BATCH), 256>>>(x, y, bout);
}